// round 4
// baseline (speedup 1.0000x reference)
#include <cuda_runtime.h>
#include <math.h>

// ---------------- problem constants ----------------
#define L_    2
#define D_    256
#define DFF_  1024
#define NH_   8
#define NP_   4
#define CIN_  512
#define B_    8
#define HH_   64
#define WW_   64
#define HW_   4096
#define EPS_  1e-5f

// ---------------- GEMM tiling ----------------
#define BM 128
#define BN 128
#define BK 8

// ---------------- scratch (device globals; allocation-free) ----------------
__device__ float g_src [B_*HW_*D_];
__device__ float g_q   [B_*HW_*D_];
__device__ float g_val [B_*HW_*D_];
__device__ float g_samp[B_*HW_*D_];
__device__ float g_tmp [B_*HW_*D_];
__device__ float g_ffn [B_*HW_*DFF_];
__device__ float g_loc [B_*HW_*NH_*NP_*2];
__device__ float g_attw[B_*HW_*NH_*NP_];

// ============================================================
// Generic GEMM: C[M,N] = A[M,K] @ B[K,N] + bias[N]  (opt ReLU)
// A row-major, B row-major. M%128==0, N%128==0, K%8==0.
// ============================================================
__global__ void __launch_bounds__(256) gemm_nn_kernel(
    const float* __restrict__ A, const float* __restrict__ Bm,
    const float* __restrict__ bias, float* __restrict__ C,
    int M, int N, int K, int relu)
{
    __shared__ __align__(16) float As[BK][BM + 4];
    __shared__ __align__(16) float Bs[BK][BN + 4];
    int tid = threadIdx.x;
    int tx = tid & 15, ty = tid >> 4;
    int bm = blockIdx.x * BM, bn = blockIdx.y * BN;

    float acc[8][8];
#pragma unroll
    for (int i = 0; i < 8; i++)
#pragma unroll
        for (int j = 0; j < 8; j++) acc[i][j] = 0.f;

    int ar  = tid >> 1;          // 0..127 (m within tile)
    int ac  = (tid & 1) * 4;     // k offset 0 or 4
    int bk  = tid >> 5;          // 0..7 (k)
    int bn4 = (tid & 31) * 4;    // n offset

    const float* Ap = A  + (size_t)(bm + ar) * K + ac;
    const float* Bp = Bm + (size_t)bk * N + bn + bn4;

    for (int k0 = 0; k0 < K; k0 += BK) {
        float4 av = *(const float4*)(Ap + k0);
        As[ac + 0][ar] = av.x; As[ac + 1][ar] = av.y;
        As[ac + 2][ar] = av.z; As[ac + 3][ar] = av.w;
        float4 bv = *(const float4*)(Bp + (size_t)k0 * N);
        *(float4*)&Bs[bk][bn4] = bv;
        __syncthreads();
#pragma unroll
        for (int kk = 0; kk < BK; kk++) {
            float4 a0 = *(const float4*)&As[kk][ty * 8];
            float4 a1 = *(const float4*)&As[kk][ty * 8 + 4];
            float4 b0 = *(const float4*)&Bs[kk][tx * 8];
            float4 b1 = *(const float4*)&Bs[kk][tx * 8 + 4];
            float a[8] = {a0.x, a0.y, a0.z, a0.w, a1.x, a1.y, a1.z, a1.w};
            float b[8] = {b0.x, b0.y, b0.z, b0.w, b1.x, b1.y, b1.z, b1.w};
#pragma unroll
            for (int i = 0; i < 8; i++)
#pragma unroll
                for (int j = 0; j < 8; j++) acc[i][j] += a[i] * b[j];
        }
        __syncthreads();
    }

#pragma unroll
    for (int i = 0; i < 8; i++) {
        int m = bm + ty * 8 + i;
#pragma unroll
        for (int j = 0; j < 8; j += 4) {
            int n = bn + tx * 8 + j;
            float4 v;
            v.x = acc[i][j + 0] + bias[n + 0];
            v.y = acc[i][j + 1] + bias[n + 1];
            v.z = acc[i][j + 2] + bias[n + 2];
            v.w = acc[i][j + 3] + bias[n + 3];
            if (relu) {
                v.x = fmaxf(v.x, 0.f); v.y = fmaxf(v.y, 0.f);
                v.z = fmaxf(v.z, 0.f); v.w = fmaxf(v.w, 0.f);
            }
            *(float4*)&C[(size_t)m * N + n] = v;
        }
    }
}

// ============================================================
// proj_in: src[b,hw,d] = relu(BN(sum_c x[b,c,hw]*W_in[d,c]))
// A[m=hw,k=c] = x[(b*CIN+c)*HW + hw]  (contiguous in m)
// B[n=d,k=c]  = W_in[d*CIN + c]       (contiguous in k)
// ============================================================
__global__ void __launch_bounds__(256) proj_in_kernel(
    const float* __restrict__ x, const float* __restrict__ Win,
    const float* __restrict__ gg, const float* __restrict__ bb,
    const float* __restrict__ mm, const float* __restrict__ vv,
    float* __restrict__ src)
{
    __shared__ __align__(16) float As[BK][BM + 4];
    __shared__ __align__(16) float Bs[BK][BN + 4];
    int tid = threadIdx.x;
    int tx = tid & 15, ty = tid >> 4;
    int b = blockIdx.z;
    int bm = blockIdx.x * BM, bn = blockIdx.y * BN;

    float acc[8][8];
#pragma unroll
    for (int i = 0; i < 8; i++)
#pragma unroll
        for (int j = 0; j < 8; j++) acc[i][j] = 0.f;

    int ak  = tid >> 5;           // k 0..7
    int am4 = (tid & 31) * 4;     // m offset
    int br  = tid >> 1;           // n 0..127
    int bc  = (tid & 1) * 4;      // k offset

    const float* Ap = x   + ((size_t)b * CIN_ + ak) * HW_ + bm + am4;
    const float* Bp = Win + (size_t)(bn + br) * CIN_ + bc;

    for (int k0 = 0; k0 < CIN_; k0 += BK) {
        float4 av = *(const float4*)(Ap + (size_t)k0 * HW_);
        *(float4*)&As[ak][am4] = av;
        float4 bv = *(const float4*)(Bp + k0);
        Bs[bc + 0][br] = bv.x; Bs[bc + 1][br] = bv.y;
        Bs[bc + 2][br] = bv.z; Bs[bc + 3][br] = bv.w;
        __syncthreads();
#pragma unroll
        for (int kk = 0; kk < BK; kk++) {
            float4 a0 = *(const float4*)&As[kk][ty * 8];
            float4 a1 = *(const float4*)&As[kk][ty * 8 + 4];
            float4 b0 = *(const float4*)&Bs[kk][tx * 8];
            float4 b1 = *(const float4*)&Bs[kk][tx * 8 + 4];
            float a[8] = {a0.x, a0.y, a0.z, a0.w, a1.x, a1.y, a1.z, a1.w};
            float bq[8] = {b0.x, b0.y, b0.z, b0.w, b1.x, b1.y, b1.z, b1.w};
#pragma unroll
            for (int i = 0; i < 8; i++)
#pragma unroll
                for (int j = 0; j < 8; j++) acc[i][j] += a[i] * bq[j];
        }
        __syncthreads();
    }

#pragma unroll
    for (int i = 0; i < 8; i++) {
        int m = bm + ty * 8 + i;  // hw
#pragma unroll
        for (int j = 0; j < 8; j += 4) {
            int n = bn + tx * 8 + j;  // d
            float4 v;
            float t0 = (acc[i][j+0] - mm[n+0]) * rsqrtf(vv[n+0] + EPS_) * gg[n+0] + bb[n+0];
            float t1 = (acc[i][j+1] - mm[n+1]) * rsqrtf(vv[n+1] + EPS_) * gg[n+1] + bb[n+1];
            float t2 = (acc[i][j+2] - mm[n+2]) * rsqrtf(vv[n+2] + EPS_) * gg[n+2] + bb[n+2];
            float t3 = (acc[i][j+3] - mm[n+3]) * rsqrtf(vv[n+3] + EPS_) * gg[n+3] + bb[n+3];
            v.x = fmaxf(t0, 0.f); v.y = fmaxf(t1, 0.f);
            v.z = fmaxf(t2, 0.f); v.w = fmaxf(t3, 0.f);
            *(float4*)&src[((size_t)b * HW_ + m) * D_ + n] = v;
        }
    }
}

// ============================================================
// proj_out: out[b,c,hw] = relu(BN(sum_d q[b,hw,d]*W_out[c,d]))
// Roles: M' = c (rows of W_out), N' = hw, K = d.
// A[m'=c,k] = W_out[c*D+k]; B[k,n'=hw] = q[(b*HW+hw)*D+k]
// ============================================================
__global__ void __launch_bounds__(256) proj_out_kernel(
    const float* __restrict__ q, const float* __restrict__ Wout,
    const float* __restrict__ gg, const float* __restrict__ bb,
    const float* __restrict__ mm, const float* __restrict__ vv,
    float* __restrict__ out)
{
    __shared__ __align__(16) float As[BK][BM + 4];
    __shared__ __align__(16) float Bs[BK][BN + 4];
    int tid = threadIdx.x;
    int tx = tid & 15, ty = tid >> 4;
    int b = blockIdx.z;
    int bm = blockIdx.x * BM;   // c
    int bn = blockIdx.y * BN;   // hw

    float acc[8][8];
#pragma unroll
    for (int i = 0; i < 8; i++)
#pragma unroll
        for (int j = 0; j < 8; j++) acc[i][j] = 0.f;

    int ar = tid >> 1;          // c 0..127
    int ac = (tid & 1) * 4;     // k offset
    int br = tid >> 1;          // hw 0..127
    int bc = (tid & 1) * 4;     // k offset

    const float* Ap = Wout + (size_t)(bm + ar) * D_ + ac;
    const float* Bp = q    + ((size_t)b * HW_ + bn + br) * D_ + bc;

    for (int k0 = 0; k0 < D_; k0 += BK) {
        float4 av = *(const float4*)(Ap + k0);
        As[ac + 0][ar] = av.x; As[ac + 1][ar] = av.y;
        As[ac + 2][ar] = av.z; As[ac + 3][ar] = av.w;
        float4 bv = *(const float4*)(Bp + k0);
        Bs[bc + 0][br] = bv.x; Bs[bc + 1][br] = bv.y;
        Bs[bc + 2][br] = bv.z; Bs[bc + 3][br] = bv.w;
        __syncthreads();
#pragma unroll
        for (int kk = 0; kk < BK; kk++) {
            float4 a0 = *(const float4*)&As[kk][ty * 8];
            float4 a1 = *(const float4*)&As[kk][ty * 8 + 4];
            float4 b0 = *(const float4*)&Bs[kk][tx * 8];
            float4 b1 = *(const float4*)&Bs[kk][tx * 8 + 4];
            float a[8] = {a0.x, a0.y, a0.z, a0.w, a1.x, a1.y, a1.z, a1.w};
            float bq[8] = {b0.x, b0.y, b0.z, b0.w, b1.x, b1.y, b1.z, b1.w};
#pragma unroll
            for (int i = 0; i < 8; i++)
#pragma unroll
                for (int j = 0; j < 8; j++) acc[i][j] += a[i] * bq[j];
        }
        __syncthreads();
    }

#pragma unroll
    for (int i = 0; i < 8; i++) {
        int c = bm + ty * 8 + i;
        float rs = rsqrtf(vv[c] + EPS_);
        float sc = rs * gg[c];
        float sh = bb[c] - mm[c] * sc;
#pragma unroll
        for (int j = 0; j < 8; j += 4) {
            int hw = bn + tx * 8 + j;
            float4 v;
            v.x = fmaxf(acc[i][j+0] * sc + sh, 0.f);
            v.y = fmaxf(acc[i][j+1] * sc + sh, 0.f);
            v.z = fmaxf(acc[i][j+2] * sc + sh, 0.f);
            v.w = fmaxf(acc[i][j+3] * sc + sh, 0.f);
            *(float4*)&out[((size_t)b * CIN_ + c) * HW_ + hw] = v;
        }
    }
}

// ============================================================
// q init: broadcast query_embed over batch
// ============================================================
__global__ void init_q_kernel(const float* __restrict__ qe, float* __restrict__ q)
{
    int i = blockIdx.x * blockDim.x + threadIdx.x;
    if (i < B_ * HW_ * D_) q[i] = qe[i % (HW_ * D_)];
}

// ============================================================
// offsets + attention softmax + sample locations
// block = 96 threads per query row; grid = B*HW
// ============================================================
__global__ void __launch_bounds__(96) offattn_kernel(
    const float* __restrict__ q,
    const float* __restrict__ Woff, const float* __restrict__ boff,
    const float* __restrict__ Wattn, const float* __restrict__ battn,
    float* __restrict__ loc, float* __restrict__ attw)
{
    int row = blockIdx.x;            // b*HW + hw
    int hw = row & (HW_ - 1);
    __shared__ float qs[D_];
    __shared__ float logits[96];
    int t = threadIdx.x;
    for (int i = t; i < D_; i += 96) qs[i] = q[(size_t)row * D_ + i];
    __syncthreads();

    float acc;
    if (t < 64) {
        acc = boff[t];
        for (int k = 0; k < D_; k++) acc += qs[k] * Woff[k * 64 + t];
    } else {
        int c = t - 64;
        acc = battn[c];
        for (int k = 0; k < D_; k++) acc += qs[k] * Wattn[k * 32 + c];
    }
    logits[t] = acc;
    __syncthreads();

    if (t < 32) {
        int h = t / NP_, p = t % NP_;
        float mx = -1e30f;
#pragma unroll
        for (int pp = 0; pp < NP_; pp++) mx = fmaxf(mx, logits[64 + h * NP_ + pp]);
        float s = 0.f;
#pragma unroll
        for (int pp = 0; pp < NP_; pp++) s += expf(logits[64 + h * NP_ + pp] - mx);
        float w = expf(logits[64 + h * NP_ + p] - mx) / s;
        attw[(size_t)row * 32 + t] = w;

        float offx = logits[(h * NP_ + p) * 2 + 0];
        float offy = logits[(h * NP_ + p) * 2 + 1];
        int py = hw / WW_, px = hw % WW_;
        float rx = (px + 0.5f) / WW_;
        float ry = (py + 0.5f) / HH_;
        loc[((size_t)row * 32 + t) * 2 + 0] = rx + offx / WW_;
        loc[((size_t)row * 32 + t) * 2 + 1] = ry + offy / HH_;
    }
}

// ============================================================
// deformable bilinear sampling + attention-weighted sum
// warp per (query,head), lane = channel within head (dh=32)
// ============================================================
__global__ void __launch_bounds__(256) sample_kernel(
    const float* __restrict__ val, const float* __restrict__ loc,
    const float* __restrict__ attw, float* __restrict__ out)
{
    int row = blockIdx.x;                 // b*HW + q
    int b = row >> 12;                    // / HW_
    int h = threadIdx.x >> 5;
    int lane = threadIdx.x & 31;

    const float* lp = loc  + ((size_t)row * 32 + h * NP_) * 2;
    const float* wp = attw + (size_t)row * 32 + h * NP_;
    float acc = 0.f;
#pragma unroll
    for (int p = 0; p < NP_; p++) {
        float lx = lp[p * 2 + 0], ly = lp[p * 2 + 1];
        float w = wp[p];
        float gx = lx * WW_ - 0.5f;
        float gy = ly * HH_ - 0.5f;
        float x0f = floorf(gx), y0f = floorf(gy);
        float wx = gx - x0f, wy = gy - y0f;
        int x0 = (int)x0f, y0 = (int)y0f;
        float v = 0.f;
#pragma unroll
        for (int dy = 0; dy < 2; dy++) {
#pragma unroll
            for (int dx = 0; dx < 2; dx++) {
                int xi = x0 + dx, yi = y0 + dy;
                if (xi >= 0 && xi < WW_ && yi >= 0 && yi < HH_) {
                    float cw = (dx ? wx : 1.f - wx) * (dy ? wy : 1.f - wy);
                    v += cw * val[((size_t)b * HW_ + yi * WW_ + xi) * D_ + h * 32 + lane];
                }
            }
        }
        acc += w * v;
    }
    out[(size_t)row * D_ + h * 32 + lane] = acc;
}

// ============================================================
// q = LayerNorm(q + delta) * g + b ; block = 256 = D
// ============================================================
__global__ void __launch_bounds__(256) add_ln_kernel(
    float* __restrict__ q, const float* __restrict__ delta,
    const float* __restrict__ g, const float* __restrict__ b)
{
    int row = blockIdx.x;
    int t = threadIdx.x;
    __shared__ float red[256];
    __shared__ float s_mean, s_var;
    size_t base = (size_t)row * D_;
    float v = q[base + t] + delta[base + t];
    red[t] = v;
    __syncthreads();
    for (int s = 128; s > 0; s >>= 1) {
        if (t < s) red[t] += red[t + s];
        __syncthreads();
    }
    if (t == 0) s_mean = red[0] * (1.f / D_);
    __syncthreads();
    float d = v - s_mean;
    red[t] = d * d;
    __syncthreads();
    for (int s = 128; s > 0; s >>= 1) {
        if (t < s) red[t] += red[t + s];
        __syncthreads();
    }
    if (t == 0) s_var = red[0] * (1.f / D_);
    __syncthreads();
    q[base + t] = d * rsqrtf(s_var + EPS_) * g[t] + b[t];
}

// ============================================================
// host launcher
// ============================================================
extern "C" void kernel_launch(void* const* d_in, const int* in_sizes, int n_in,
                              void* d_out, int out_size)
{
    const float* x      = (const float*)d_in[0];
    const float* W_in   = (const float*)d_in[1];
    const float* bn1_g  = (const float*)d_in[2];
    const float* bn1_b  = (const float*)d_in[3];
    const float* bn1_m  = (const float*)d_in[4];
    const float* bn1_v  = (const float*)d_in[5];
    const float* qembed = (const float*)d_in[6];
    const float* Woff   = (const float*)d_in[7];
    const float* boff   = (const float*)d_in[8];
    const float* Wattn  = (const float*)d_in[9];
    const float* battn  = (const float*)d_in[10];
    const float* Wval   = (const float*)d_in[11];
    const float* bval   = (const float*)d_in[12];
    const float* Wo     = (const float*)d_in[13];
    const float* bo     = (const float*)d_in[14];
    const float* ln1_g  = (const float*)d_in[15];
    const float* ln1_b  = (const float*)d_in[16];
    const float* W1     = (const float*)d_in[17];
    const float* b1     = (const float*)d_in[18];
    const float* W2     = (const float*)d_in[19];
    const float* b2     = (const float*)d_in[20];
    const float* ln2_g  = (const float*)d_in[21];
    const float* ln2_b  = (const float*)d_in[22];
    const float* W_out  = (const float*)d_in[23];
    const float* bn2_g  = (const float*)d_in[24];
    const float* bn2_b  = (const float*)d_in[25];
    const float* bn2_m  = (const float*)d_in[26];
    const float* bn2_v  = (const float*)d_in[27];
    float* out = (float*)d_out;

    float *src, *q, *val, *samp, *tmp, *ffn, *loc, *attw;
    cudaGetSymbolAddress((void**)&src,  g_src);
    cudaGetSymbolAddress((void**)&q,    g_q);
    cudaGetSymbolAddress((void**)&val,  g_val);
    cudaGetSymbolAddress((void**)&samp, g_samp);
    cudaGetSymbolAddress((void**)&tmp,  g_tmp);
    cudaGetSymbolAddress((void**)&ffn,  g_ffn);
    cudaGetSymbolAddress((void**)&loc,  g_loc);
    cudaGetSymbolAddress((void**)&attw, g_attw);

    dim3 blk(256);
    const int M = B_ * HW_;  // 32768

    proj_in_kernel<<<dim3(HW_ / BM, D_ / BN, B_), blk>>>(
        x, W_in, bn1_g, bn1_b, bn1_m, bn1_v, src);

    int tot = B_ * HW_ * D_;
    init_q_kernel<<<(tot + 255) / 256, 256>>>(qembed, q);

    for (int l = 0; l < L_; l++) {
        gemm_nn_kernel<<<dim3(M / BM, D_ / BN), blk>>>(
            src, Wval + (size_t)l * D_ * D_, bval + l * D_, val, M, D_, D_, 0);

        offattn_kernel<<<M, 96>>>(
            q, Woff + (size_t)l * D_ * 64, boff + l * 64,
            Wattn + (size_t)l * D_ * 32, battn + l * 32, loc, attw);

        sample_kernel<<<M, 256>>>(val, loc, attw, samp);

        gemm_nn_kernel<<<dim3(M / BM, D_ / BN), blk>>>(
            samp, Wo + (size_t)l * D_ * D_, bo + l * D_, tmp, M, D_, D_, 0);

        add_ln_kernel<<<M, D_>>>(q, tmp, ln1_g + l * D_, ln1_b + l * D_);

        gemm_nn_kernel<<<dim3(M / BM, DFF_ / BN), blk>>>(
            q, W1 + (size_t)l * D_ * DFF_, b1 + l * DFF_, ffn, M, DFF_, D_, 1);

        gemm_nn_kernel<<<dim3(M / BM, D_ / BN), blk>>>(
            ffn, W2 + (size_t)l * DFF_ * D_, b2 + l * D_, tmp, M, D_, DFF_, 0);

        add_ln_kernel<<<M, D_>>>(q, tmp, ln2_g + l * D_, ln2_b + l * D_);
    }

    proj_out_kernel<<<dim3(CIN_ / BM, HW_ / BN, B_), blk>>>(
        q, W_out, bn2_g, bn2_b, bn2_m, bn2_v, out);
}

// round 5
// speedup vs baseline: 2.7964x; 2.7964x over previous
#include <cuda_runtime.h>
#include <math.h>
#include <stdint.h>

// ---------------- problem constants ----------------
#define L_    2
#define D_    256
#define DFF_  1024
#define NH_   8
#define NP_   4
#define CIN_  512
#define B_    8
#define HH_   64
#define WW_   64
#define HW_   4096
#define EPS_  1e-5f

// ---------------- GEMM tiling ----------------
#define BM 128
#define BN 128
#define BK 16

// ---------------- scratch (device globals; allocation-free) ----------------
__device__ __align__(128) float g_src   [B_*HW_*D_];
__device__ __align__(128) float g_q     [B_*HW_*D_];
__device__ __align__(128) float g_val   [B_*HW_*D_];
__device__ __align__(128) float g_samp  [B_*HW_*D_];
__device__ __align__(128) float g_tmp   [B_*HW_*D_];
__device__ __align__(128) float g_ffn   [B_*HW_*DFF_];
__device__ __align__(128) float g_loc   [B_*HW_*NH_*NP_*2];
__device__ __align__(128) float g_attw  [B_*HW_*NH_*NP_];
__device__ __align__(128) float g_logits[B_*HW_*128];
__device__ __align__(128) float g_wcat  [L_*D_*128];
__device__ __align__(128) float g_bcat  [L_*128];

// ---------------- small helpers ----------------
__device__ __forceinline__ void cp16(float* dst, const float* src) {
    uint32_t d = (uint32_t)__cvta_generic_to_shared(dst);
    asm volatile("cp.async.cg.shared.global [%0], [%1], 16;\n" :: "r"(d), "l"(src));
}
__device__ __forceinline__ uint32_t f2tf(float f) {
    uint32_t u; asm("cvt.rna.tf32.f32 %0, %1;" : "=r"(u) : "f"(f)); return u;
}
__device__ __forceinline__ void mma8(float* c, const uint32_t* a, const uint32_t* b) {
    asm volatile(
        "mma.sync.aligned.m16n8k8.row.col.f32.tf32.tf32.f32 "
        "{%0,%1,%2,%3},{%4,%5,%6,%7},{%8,%9},{%0,%1,%2,%3};"
        : "+f"(c[0]), "+f"(c[1]), "+f"(c[2]), "+f"(c[3])
        : "r"(a[0]), "r"(a[1]), "r"(a[2]), "r"(a[3]), "r"(b[0]), "r"(b[1]));
}

// ============================================================
// TF32 tensor-core GEMM.  C[M,N] = op(A) @ op(B) + epilogue
//  AMODE 0: A row-major [M,K], lda = row stride
//  AMODE 1: A k-major   A[k][m] with row stride lda (e.g. NCHW x)
//  BMODE 0: B row-major [K,N], ldb = row stride  (cp.async path)
//  BMODE 1: B[k][n] = Bg[n*ldb + k]  (transpose-staged via LDG+STS)
//  EPI 0: + p0[n] bias, optional relu
//  EPI 1: BN per-n (p0=g,p1=b,p2=mean,p3=var) + relu
//  EPI 2: BN per-m + relu
// Block: 256 thr (8 warps, 2x4), tile 128x128x16, warp tile 64x32.
// ============================================================
template<int AMODE, int BMODE, int EPI>
__global__ void __launch_bounds__(256) gemm_tf32(
    const float* __restrict__ A, int lda, size_t sA,
    const float* __restrict__ Bg, int ldb, size_t sB,
    float* __restrict__ C, int ldc, size_t sC,
    const float* __restrict__ p0, const float* __restrict__ p1,
    const float* __restrict__ p2, const float* __restrict__ p3,
    int K, int relu)
{
    constexpr int AST = (AMODE == 0) ? 20 : 136;   // SMEM strides (bank-conflict-free)
    constexpr int ARS = (AMODE == 0) ? BM : BK;
    __shared__ float As[2][ARS * AST];
    __shared__ float Bs[2][BK * 136];

    int tid = threadIdx.x;
    int bm = blockIdx.x * BM, bn = blockIdx.y * BN;
    const float* Ab = A  + (size_t)blockIdx.z * sA;
    const float* Bb = Bg + (size_t)blockIdx.z * sB;
    float*       Cb = C  + (size_t)blockIdx.z * sC;

    float acc[4][4][4];
#pragma unroll
    for (int i = 0; i < 4; i++)
#pragma unroll
        for (int j = 0; j < 4; j++)
#pragma unroll
            for (int r = 0; r < 4; r++) acc[i][j][r] = 0.f;

    int lane = tid & 31, wid = tid >> 5;
    int wm = (wid >> 2) * 64, wn = (wid & 3) * 32;

    auto stage = [&](int s, int k0) {
        if (AMODE == 0) {
#pragma unroll
            for (int id = tid; id < 512; id += 256) {
                int r = id >> 2, c4 = (id & 3) << 2;
                cp16(&As[s][r * AST + c4], Ab + (size_t)(bm + r) * lda + k0 + c4);
            }
        } else {
#pragma unroll
            for (int id = tid; id < 512; id += 256) {
                int k = id >> 5, m4 = (id & 31) << 2;
                cp16(&As[s][k * AST + m4], Ab + (size_t)(k0 + k) * lda + bm + m4);
            }
        }
        if (BMODE == 0) {
#pragma unroll
            for (int id = tid; id < 512; id += 256) {
                int k = id >> 5, n4 = (id & 31) << 2;
                cp16(&Bs[s][k * 136 + n4], Bb + (size_t)(k0 + k) * ldb + bn + n4);
            }
            asm volatile("cp.async.commit_group;\n");
        } else {
            asm volatile("cp.async.commit_group;\n");
#pragma unroll
            for (int id = tid; id < 512; id += 256) {
                int n = id >> 2, kk = (id & 3) << 2;
                float4 v = *(const float4*)(Bb + (size_t)(bn + n) * ldb + k0 + kk);
                Bs[s][(kk + 0) * 136 + n] = v.x;
                Bs[s][(kk + 1) * 136 + n] = v.y;
                Bs[s][(kk + 2) * 136 + n] = v.z;
                Bs[s][(kk + 3) * 136 + n] = v.w;
            }
        }
    };

    stage(0, 0);
    int buf = 0;
    for (int k0 = 0; k0 < K; k0 += BK) {
        if (k0 + BK < K) {
            stage(buf ^ 1, k0 + BK);
            asm volatile("cp.async.wait_group 1;\n");
        } else {
            asm volatile("cp.async.wait_group 0;\n");
        }
        __syncthreads();

#pragma unroll
        for (int ks = 0; ks < 2; ks++) {
            uint32_t af[4][4], bf[4][2];
            int c0 = ks * 8 + (lane & 3);
            int rr = lane >> 2;
#pragma unroll
            for (int mt = 0; mt < 4; mt++) {
                int r0 = wm + mt * 16 + rr;
                if (AMODE == 0) {
                    af[mt][0] = f2tf(As[buf][r0 * AST + c0]);
                    af[mt][1] = f2tf(As[buf][(r0 + 8) * AST + c0]);
                    af[mt][2] = f2tf(As[buf][r0 * AST + c0 + 4]);
                    af[mt][3] = f2tf(As[buf][(r0 + 8) * AST + c0 + 4]);
                } else {
                    af[mt][0] = f2tf(As[buf][c0 * AST + r0]);
                    af[mt][1] = f2tf(As[buf][c0 * AST + r0 + 8]);
                    af[mt][2] = f2tf(As[buf][(c0 + 4) * AST + r0]);
                    af[mt][3] = f2tf(As[buf][(c0 + 4) * AST + r0 + 8]);
                }
            }
#pragma unroll
            for (int nt = 0; nt < 4; nt++) {
                int nb = wn + nt * 8 + rr;
                bf[nt][0] = f2tf(Bs[buf][c0 * 136 + nb]);
                bf[nt][1] = f2tf(Bs[buf][(c0 + 4) * 136 + nb]);
            }
#pragma unroll
            for (int mt = 0; mt < 4; mt++)
#pragma unroll
                for (int nt = 0; nt < 4; nt++)
                    mma8(acc[mt][nt], af[mt], bf[nt]);
        }
        __syncthreads();
        buf ^= 1;
    }

    // ---------------- epilogue ----------------
    int tig = lane & 3, grp = lane >> 2;
#pragma unroll
    for (int mt = 0; mt < 4; mt++) {
#pragma unroll
        for (int nt = 0; nt < 4; nt++) {
            int gm = bm + wm + mt * 16 + grp;
            int gn = bn + wn + nt * 8 + tig * 2;
            float* c = acc[mt][nt];
#pragma unroll
            for (int half = 0; half < 2; half++) {
                int row = gm + half * 8;
                float v0 = c[half * 2 + 0], v1 = c[half * 2 + 1];
                if (EPI == 0) {
                    v0 += p0[gn]; v1 += p0[gn + 1];
                    if (relu) { v0 = fmaxf(v0, 0.f); v1 = fmaxf(v1, 0.f); }
                } else if (EPI == 1) {
                    float s0 = rsqrtf(p3[gn] + EPS_) * p0[gn];
                    float s1 = rsqrtf(p3[gn + 1] + EPS_) * p0[gn + 1];
                    v0 = fmaxf((v0 - p2[gn]) * s0 + p1[gn], 0.f);
                    v1 = fmaxf((v1 - p2[gn + 1]) * s1 + p1[gn + 1], 0.f);
                } else {
                    float s = rsqrtf(p3[row] + EPS_) * p0[row];
                    float h = p1[row] - p2[row] * s;
                    v0 = fmaxf(v0 * s + h, 0.f);
                    v1 = fmaxf(v1 * s + h, 0.f);
                }
                float2 o; o.x = v0; o.y = v1;
                *(float2*)&Cb[(size_t)row * ldc + gn] = o;
            }
        }
    }
}

// ============================================================
// weight-prep: concat [Woff | Wattn | 0] -> wcat[L][D][128], biases -> bcat
// ============================================================
__global__ void prep_wcat_kernel(const float* __restrict__ Woff,
                                 const float* __restrict__ Wattn,
                                 float* __restrict__ wcat)
{
    int i = blockIdx.x * 256 + threadIdx.x;
    if (i >= L_ * D_ * 128) return;
    int l = i / (D_ * 128);
    int r = (i / 128) % D_;
    int c = i % 128;
    float v = 0.f;
    if (c < 64)      v = Woff[((size_t)l * D_ + r) * 64 + c];
    else if (c < 96) v = Wattn[((size_t)l * D_ + r) * 32 + (c - 64)];
    wcat[i] = v;
}
__global__ void prep_bcat_kernel(const float* __restrict__ boff,
                                 const float* __restrict__ battn,
                                 float* __restrict__ bcat)
{
    int i = threadIdx.x + blockIdx.x * 256;
    if (i >= L_ * 128) return;
    int l = i / 128, c = i % 128;
    float v = 0.f;
    if (c < 64)      v = boff[l * 64 + c];
    else if (c < 96) v = battn[l * 32 + (c - 64)];
    bcat[i] = v;
}

// ============================================================
// q init: broadcast query_embed over batch
// ============================================================
__global__ void init_q_kernel(const float* __restrict__ qe, float* __restrict__ q)
{
    int i = blockIdx.x * blockDim.x + threadIdx.x;
    if (i < B_ * HW_ * D_) q[i] = qe[i % (HW_ * D_)];
}

// ============================================================
// softmax over NP + sample-location compute from GEMM logits
// logits row layout: [0:64) offsets (h,p,xy), [64:96) attn, [96:128) pad
// 256 threads = 8 rows per block
// ============================================================
__global__ void __launch_bounds__(256) postproc_kernel(
    const float* __restrict__ lg, float* __restrict__ loc, float* __restrict__ attw)
{
    int row = blockIdx.x * 8 + (threadIdx.x >> 5);
    int t = threadIdx.x & 31;
    const float* p = lg + (size_t)row * 128;
    int h = t >> 2, pp = t & 3;
    float l0 = p[64 + h * 4 + 0], l1 = p[64 + h * 4 + 1];
    float l2 = p[64 + h * 4 + 2], l3 = p[64 + h * 4 + 3];
    float mx = fmaxf(fmaxf(l0, l1), fmaxf(l2, l3));
    float e0 = expf(l0 - mx), e1 = expf(l1 - mx), e2 = expf(l2 - mx), e3 = expf(l3 - mx);
    float s = e0 + e1 + e2 + e3;
    float my = (pp == 0) ? e0 : (pp == 1) ? e1 : (pp == 2) ? e2 : e3;
    attw[(size_t)row * 32 + t] = my / s;

    float offx = p[(h * 4 + pp) * 2 + 0];
    float offy = p[(h * 4 + pp) * 2 + 1];
    int hw = row & (HW_ - 1);
    float rx = ((hw & (WW_ - 1)) + 0.5f) * (1.f / WW_);
    float ry = ((hw >> 6) + 0.5f) * (1.f / HH_);
    loc[((size_t)row * 32 + t) * 2 + 0] = rx + offx * (1.f / WW_);
    loc[((size_t)row * 32 + t) * 2 + 1] = ry + offy * (1.f / HH_);
}

// ============================================================
// deformable bilinear sampling + attention-weighted sum
// warp per (query,head), lane = channel within head (dh=32)
// ============================================================
__global__ void __launch_bounds__(256) sample_kernel(
    const float* __restrict__ val, const float* __restrict__ loc,
    const float* __restrict__ attw, float* __restrict__ out)
{
    int row = blockIdx.x;                 // b*HW + q
    int b = row >> 12;
    int h = threadIdx.x >> 5;
    int lane = threadIdx.x & 31;

    const float* lp = loc  + ((size_t)row * 32 + h * NP_) * 2;
    const float* wp = attw + (size_t)row * 32 + h * NP_;
    float acc = 0.f;
#pragma unroll
    for (int p = 0; p < NP_; p++) {
        float lx = lp[p * 2 + 0], ly = lp[p * 2 + 1];
        float w = wp[p];
        float gx = lx * WW_ - 0.5f;
        float gy = ly * HH_ - 0.5f;
        float x0f = floorf(gx), y0f = floorf(gy);
        float wx = gx - x0f, wy = gy - y0f;
        int x0 = (int)x0f, y0 = (int)y0f;
        float v = 0.f;
#pragma unroll
        for (int dy = 0; dy < 2; dy++) {
#pragma unroll
            for (int dx = 0; dx < 2; dx++) {
                int xi = x0 + dx, yi = y0 + dy;
                if (xi >= 0 && xi < WW_ && yi >= 0 && yi < HH_) {
                    float cw = (dx ? wx : 1.f - wx) * (dy ? wy : 1.f - wy);
                    v += cw * val[((size_t)b * HW_ + yi * WW_ + xi) * D_ + h * 32 + lane];
                }
            }
        }
        acc += w * v;
    }
    out[(size_t)row * D_ + h * 32 + lane] = acc;
}

// ============================================================
// q = LayerNorm(q + delta) * g + b ; block = 256 = D (shuffle reduce)
// ============================================================
__global__ void __launch_bounds__(256) add_ln_kernel(
    float* __restrict__ q, const float* __restrict__ delta,
    const float* __restrict__ g, const float* __restrict__ b)
{
    int row = blockIdx.x;
    int t = threadIdx.x;
    __shared__ float wsum[8];
    __shared__ float s_mean, s_var;
    size_t base = (size_t)row * D_;
    float v = q[base + t] + delta[base + t];

    float r = v;
#pragma unroll
    for (int o = 16; o > 0; o >>= 1) r += __shfl_xor_sync(0xffffffffu, r, o);
    if ((t & 31) == 0) wsum[t >> 5] = r;
    __syncthreads();
    if (t < 8) {
        float x = wsum[t];
#pragma unroll
        for (int o = 4; o > 0; o >>= 1) x += __shfl_xor_sync(0xffu, x, o);
        if (t == 0) s_mean = x * (1.f / D_);
    }
    __syncthreads();
    float d = v - s_mean;
    r = d * d;
#pragma unroll
    for (int o = 16; o > 0; o >>= 1) r += __shfl_xor_sync(0xffffffffu, r, o);
    if ((t & 31) == 0) wsum[t >> 5] = r;
    __syncthreads();
    if (t < 8) {
        float x = wsum[t];
#pragma unroll
        for (int o = 4; o > 0; o >>= 1) x += __shfl_xor_sync(0xffu, x, o);
        if (t == 0) s_var = x * (1.f / D_);
    }
    __syncthreads();
    q[base + t] = d * rsqrtf(s_var + EPS_) * g[t] + b[t];
}

// ============================================================
// host launcher
// ============================================================
extern "C" void kernel_launch(void* const* d_in, const int* in_sizes, int n_in,
                              void* d_out, int out_size)
{
    const float* x      = (const float*)d_in[0];
    const float* W_in   = (const float*)d_in[1];
    const float* bn1_g  = (const float*)d_in[2];
    const float* bn1_b  = (const float*)d_in[3];
    const float* bn1_m  = (const float*)d_in[4];
    const float* bn1_v  = (const float*)d_in[5];
    const float* qembed = (const float*)d_in[6];
    const float* Woff   = (const float*)d_in[7];
    const float* boff   = (const float*)d_in[8];
    const float* Wattn  = (const float*)d_in[9];
    const float* battn  = (const float*)d_in[10];
    const float* Wval   = (const float*)d_in[11];
    const float* bval   = (const float*)d_in[12];
    const float* Wo     = (const float*)d_in[13];
    const float* bo     = (const float*)d_in[14];
    const float* ln1_g  = (const float*)d_in[15];
    const float* ln1_b  = (const float*)d_in[16];
    const float* W1     = (const float*)d_in[17];
    const float* b1     = (const float*)d_in[18];
    const float* W2     = (const float*)d_in[19];
    const float* b2     = (const float*)d_in[20];
    const float* ln2_g  = (const float*)d_in[21];
    const float* ln2_b  = (const float*)d_in[22];
    const float* W_out  = (const float*)d_in[23];
    const float* bn2_g  = (const float*)d_in[24];
    const float* bn2_b  = (const float*)d_in[25];
    const float* bn2_m  = (const float*)d_in[26];
    const float* bn2_v  = (const float*)d_in[27];
    float* out = (float*)d_out;

    float *src, *q, *val, *samp, *tmp, *ffn, *loc, *attw, *logits, *wcat, *bcat;
    cudaGetSymbolAddress((void**)&src,    g_src);
    cudaGetSymbolAddress((void**)&q,      g_q);
    cudaGetSymbolAddress((void**)&val,    g_val);
    cudaGetSymbolAddress((void**)&samp,   g_samp);
    cudaGetSymbolAddress((void**)&tmp,    g_tmp);
    cudaGetSymbolAddress((void**)&ffn,    g_ffn);
    cudaGetSymbolAddress((void**)&loc,    g_loc);
    cudaGetSymbolAddress((void**)&attw,   g_attw);
    cudaGetSymbolAddress((void**)&logits, g_logits);
    cudaGetSymbolAddress((void**)&wcat,   g_wcat);
    cudaGetSymbolAddress((void**)&bcat,   g_bcat);

    const int M = B_ * HW_;  // 32768
    dim3 blk(256);

    // weight prep (cheap, deterministic)
    prep_wcat_kernel<<<(L_ * D_ * 128 + 255) / 256, 256>>>(Woff, Wattn, wcat);
    prep_bcat_kernel<<<1, 256>>>(boff, battn, bcat);

    // proj_in: AMODE1 (x k-major), BMODE1 (W_in cols), EPI1 (BN per-n=d)
    gemm_tf32<1, 1, 1><<<dim3(HW_ / BM, D_ / BN, B_), blk>>>(
        x, HW_, (size_t)CIN_ * HW_,
        W_in, CIN_, 0,
        src, D_, (size_t)HW_ * D_,
        bn1_g, bn1_b, bn1_m, bn1_v, CIN_, 0);

    init_q_kernel<<<(B_ * HW_ * D_ + 255) / 256, 256>>>(qembed, q);

    for (int l = 0; l < L_; l++) {
        // value projection
        gemm_tf32<0, 0, 0><<<dim3(M / BM, D_ / BN, 1), blk>>>(
            src, D_, 0, Wval + (size_t)l * D_ * D_, D_, 0,
            val, D_, 0, bval + l * D_, nullptr, nullptr, nullptr, D_, 0);

        // fused offset+attn logits GEMM (N=128 padded)
        gemm_tf32<0, 0, 0><<<dim3(M / BM, 1, 1), blk>>>(
            q, D_, 0, wcat + (size_t)l * D_ * 128, 128, 0,
            logits, 128, 0, bcat + l * 128, nullptr, nullptr, nullptr, D_, 0);

        postproc_kernel<<<M / 8, 256>>>(logits, loc, attw);

        sample_kernel<<<M, 256>>>(val, loc, attw, samp);

        gemm_tf32<0, 0, 0><<<dim3(M / BM, D_ / BN, 1), blk>>>(
            samp, D_, 0, Wo + (size_t)l * D_ * D_, D_, 0,
            tmp, D_, 0, bo + l * D_, nullptr, nullptr, nullptr, D_, 0);

        add_ln_kernel<<<M, D_>>>(q, tmp, ln1_g + l * D_, ln1_b + l * D_);

        gemm_tf32<0, 0, 0><<<dim3(M / BM, DFF_ / BN, 1), blk>>>(
            q, D_, 0, W1 + (size_t)l * D_ * DFF_, DFF_, 0,
            ffn, DFF_, 0, b1 + l * DFF_, nullptr, nullptr, nullptr, D_, 1);

        gemm_tf32<0, 0, 0><<<dim3(M / BM, D_ / BN, 1), blk>>>(
            ffn, DFF_, 0, W2 + (size_t)l * DFF_ * D_, D_, 0,
            tmp, D_, 0, b2 + l * D_, nullptr, nullptr, nullptr, DFF_, 0);

        add_ln_kernel<<<M, D_>>>(q, tmp, ln2_g + l * D_, ln2_b + l * D_);
    }

    // proj_out: AMODE0 (W_out rows = c), BMODE1 (q cols), EPI2 (BN per-m=c)
    gemm_tf32<0, 1, 2><<<dim3(CIN_ / BM, HW_ / BN, B_), blk>>>(
        W_out, D_, 0,
        q, D_, (size_t)HW_ * D_,
        out, HW_, (size_t)CIN_ * HW_,
        bn2_g, bn2_b, bn2_m, bn2_v, D_, 0);
}